// round 8
// baseline (speedup 1.0000x reference)
#include <cuda_runtime.h>
#include <cuda_bf16.h>
#include <math.h>
#include <stdint.h>

// Problem constants (fixed shapes)
#define BB 4
#define HH 64
#define WW 64
#define FF 256
#define CC 19
#define SS 256
#define TWOS (2*SS)            // 512
#define NN (BB*HH*WW)          // 16384 pixels
#define MM (CC*TWOS)           // 9728 memory vectors

// Scratch (static device globals; no allocation at runtime)
__device__ __nv_bfloat16 g_A[NN * FF];   // normalized feats, [n][f] row-major (8 MB)
__device__ __nv_bfloat16 g_Bm[MM * FF];  // normalized memory, [m][f] row-major (5 MB)
__device__ float g_total[NN];            // per-pixel sum of exp(cos/temp)
__device__ float g_blocksum[NN];         // per-pixel own-block sum of exp
__device__ float g_owncos[NN * TWOS];    // per-pixel own-class-block cos (33.5 MB)
__device__ float g_pixterm[NN];          // per-pixel positive-term sum

// ---------------------------------------------------------------------------
// exp(2*c) via MUFU: exp(2c) = 2^(2c*log2 e). ex2.approx rel err ~1e-6 here
// (|2c*log2e| <= ~2.9). Keeps the FMA pipe free.
// ---------------------------------------------------------------------------
__device__ __forceinline__ float fexp2c(float c) {
    float y = c * 2.8853900817779268f;   // 2 * log2(e)
    float r;
    asm("ex2.approx.f32 %0, %1;" : "=f"(r) : "f"(y));
    return r;
}

__device__ __forceinline__ void cp16(uint32_t smem_dst, const void* gsrc) {
    asm volatile("cp.async.cg.shared.global [%0], [%1], 16;\n" :: "r"(smem_dst), "l"(gsrc));
}

__device__ __forceinline__ uint32_t smem_u32(const void* p) {
    uint32_t a;
    asm("{ .reg .u64 t; cvta.to.shared.u64 t, %1; cvt.u32.u64 %0, t; }" : "=r"(a) : "l"(p));
    return a;
}

__device__ __forceinline__ void ldm_x4(uint32_t* r, uint32_t addr) {
    asm volatile("ldmatrix.sync.aligned.m8n8.x4.shared.b16 {%0,%1,%2,%3}, [%4];"
        : "=r"(r[0]), "=r"(r[1]), "=r"(r[2]), "=r"(r[3]) : "r"(addr));
}

__device__ __forceinline__ void mma16816(float* d, const uint32_t* a, const uint32_t* b) {
    asm volatile(
        "mma.sync.aligned.m16n8k16.row.col.f32.bf16.bf16.f32 "
        "{%0,%1,%2,%3}, {%4,%5,%6,%7}, {%8,%9}, {%0,%1,%2,%3};\n"
        : "+f"(d[0]), "+f"(d[1]), "+f"(d[2]), "+f"(d[3])
        : "r"(a[0]), "r"(a[1]), "r"(a[2]), "r"(a[3]), "r"(b[0]), "r"(b[1]));
}

// ---------------------------------------------------------------------------
// K1a: normalize feats. pred_rep is (B,F,H,W). Write bf16 [n][f] row-major.
// Also zero g_total/g_blocksum (rewritten each launch -> graph-deterministic).
// ---------------------------------------------------------------------------
__global__ void k_prep_feats(const float* __restrict__ pred) {
    int t = threadIdx.x;
    int w = t & 63;
    int h = blockIdx.y * 4 + (t >> 6);
    int b = blockIdx.x;
    int n = (b * HH + h) * WW + w;
    const float* base = pred + (size_t)b * FF * HH * WW + h * WW + w;

    float sumsq = 0.0f;
    #pragma unroll 8
    for (int f = 0; f < FF; f++) {
        float v = base[f * (HH * WW)];
        sumsq += v * v;
    }
    float inv = rsqrtf(sumsq);

    for (int f0 = 0; f0 < FF; f0 += 8) {
        __nv_bfloat16 h8[8];
        #pragma unroll
        for (int j = 0; j < 8; j++)
            h8[j] = __float2bfloat16(base[(f0 + j) * (HH * WW)] * inv);
        *(uint4*)&g_A[n * FF + f0] = *(const uint4*)h8;
    }
    g_total[n] = 0.0f;
    g_blocksum[n] = 0.0f;
}

// ---------------------------------------------------------------------------
// K1b: normalize memory rows -> bf16 [m][f]. One block (128 thr) per row.
// ---------------------------------------------------------------------------
__global__ void k_prep_mem(const float* __restrict__ mem) {
    __shared__ float red[4];
    int m = blockIdx.x;
    int t = threadIdx.x;
    float2 v = *(const float2*)&mem[m * FF + 2 * t];
    float p = v.x * v.x + v.y * v.y;
    #pragma unroll
    for (int o = 16; o > 0; o >>= 1) p += __shfl_down_sync(0xffffffffu, p, o);
    if ((t & 31) == 0) red[t >> 5] = p;
    __syncthreads();
    float inv = rsqrtf(red[0] + red[1] + red[2] + red[3]);
    __nv_bfloat162 o2;
    o2.x = __float2bfloat16(v.x * inv);
    o2.y = __float2bfloat16(v.y * inv);
    *(__nv_bfloat162*)&g_Bm[m * FF + 2 * t] = o2;
}

// ---------------------------------------------------------------------------
// K2: bf16 HMMA GEMM, CTA tile 128 pix x 256 mem, warp tile 64x64
// (2 m-warps x 4 n-warps), ldmatrix + XOR swizzle, BK=64 double-buffered.
// Epilogue: MUFU exp row sums + own-block sum + own-class cos scatter.
// ---------------------------------------------------------------------------
// Dynamic smem (bytes): labels[128]@0, rowsum@512, blksum@1024,
// A bufs @2048 (2 x 16KB), B bufs @34816 (2 x 32KB). Total 100352.
#define SM_LAB   0
#define SM_PART  512
#define SM_BPART 1024
#define SM_A     2048
#define SM_B     (2048 + 32768)
#define SM_TOTAL (2048 + 32768 + 65536)

__global__ __launch_bounds__(256, 1) void k_gemm(const int* __restrict__ labels) {
    extern __shared__ __align__(1024) char dsm[];
    uint32_t sb = smem_u32(dsm);

    int tid = threadIdx.x;
    int m0 = blockIdx.x * 256;
    int n0 = blockIdx.y * 128;
    int wid = tid >> 5, lane = tid & 31;
    int wmw = wid & 1;          // pixel-dir warp (2): rows [wmw*64, +64)
    int wnw = wid >> 1;         // mem-dir warp (4): cols [wnw*64, +64)
    int g = lane >> 2, t4 = lane & 3;
    int l15 = lane & 15, l16 = lane >> 4;

    float* s_rowsum = (float*)(dsm + SM_PART);
    float* s_blksum = (float*)(dsm + SM_BPART);
    int*   s_lab    = (int*)(dsm + SM_LAB);

    if (tid < 128) {
        s_rowsum[tid] = 0.0f;
        s_blksum[tid] = 0.0f;
        s_lab[tid] = labels[n0 + tid];
    }

    float acc[4][8][4];
    #pragma unroll
    for (int mi = 0; mi < 4; mi++)
        #pragma unroll
        for (int ni = 0; ni < 8; ni++)
            #pragma unroll
            for (int q = 0; q < 4; q++) acc[mi][ni][q] = 0.0f;

    // Fill one BK=64 slice: A 1024 + B 2048 16B-chunks.
#define ISSUE(IT, BUF) do {                                                     \
        int k0_ = (IT) * 64;                                                    \
        _Pragma("unroll")                                                       \
        for (int r_ = 0; r_ < 4; r_++) {                                        \
            int id = tid + r_ * 256;          /* 0..1023 */                     \
            int row = id >> 3, c = id & 7;                                      \
            int sw = (c ^ (row & 7)) << 4;                                      \
            cp16(sb + SM_A + (BUF) * 16384 + row * 128 + sw,                    \
                 &g_A[(size_t)(n0 + row) * FF + k0_ + c * 8]);                  \
        }                                                                       \
        _Pragma("unroll")                                                       \
        for (int r_ = 0; r_ < 8; r_++) {                                        \
            int id = tid + r_ * 256;          /* 0..2047 */                     \
            int row = id >> 3, c = id & 7;                                      \
            int sw = (c ^ (row & 7)) << 4;                                      \
            cp16(sb + SM_B + (BUF) * 32768 + row * 128 + sw,                    \
                 &g_Bm[(size_t)(m0 + row) * FF + k0_ + c * 8]);                 \
        } } while (0)

    ISSUE(0, 0);
    asm volatile("cp.async.commit_group;\n");

    #pragma unroll
    for (int it = 0; it < 4; it++) {
        int buf = it & 1;
        if (it < 3) ISSUE(it + 1, buf ^ 1);
        asm volatile("cp.async.commit_group;\n");
        asm volatile("cp.async.wait_group 1;\n");
        __syncthreads();

        uint32_t Ab = sb + SM_A + buf * 16384;
        uint32_t Bb = sb + SM_B + buf * 32768;
        #pragma unroll
        for (int ks = 0; ks < 4; ks++) {
            int kc = ks * 2 + l16;
            uint32_t a[4][4], b[4][4];
            #pragma unroll
            for (int mi = 0; mi < 4; mi++) {
                int row = wmw * 64 + mi * 16 + l15;
                ldm_x4(a[mi], Ab + row * 128 + ((kc ^ (row & 7)) << 4));
            }
            #pragma unroll
            for (int nj = 0; nj < 4; nj++) {
                int row = wnw * 64 + nj * 16 + l15;
                ldm_x4(b[nj], Bb + row * 128 + ((kc ^ (row & 7)) << 4));
            }
            #pragma unroll
            for (int mi = 0; mi < 4; mi++)
                #pragma unroll
                for (int nj = 0; nj < 4; nj++) {
                    uint32_t b0[2] = { b[nj][0], b[nj][2] };
                    uint32_t b1[2] = { b[nj][1], b[nj][3] };
                    mma16816(acc[mi][2 * nj],     a[mi], b0);
                    mma16816(acc[mi][2 * nj + 1], a[mi], b1);
                }
        }
        __syncthreads();
    }
#undef ISSUE

    // Epilogue: MUFU exp + row sums + own-block sums + own-class cos scatter.
    // 256-aligned m-window always lies inside one 512-wide class block.
    int cls = m0 >> 9;
    int mbase = (m0 & 511) + wnw * 64;

    #pragma unroll
    for (int mi = 0; mi < 4; mi++) {
        int p0 = wmw * 64 + mi * 16 + g;
        int p1 = p0 + 8;
        bool own0 = (s_lab[p0] == cls);
        bool own1 = (s_lab[p1] == cls);
        float s0 = 0.0f, s1 = 0.0f;
        #pragma unroll
        for (int ni = 0; ni < 8; ni++) {
            float d0 = acc[mi][ni][0], d1 = acc[mi][ni][1];
            float d2 = acc[mi][ni][2], d3 = acc[mi][ni][3];
            s0 += fexp2c(d0) + fexp2c(d1);
            s1 += fexp2c(d2) + fexp2c(d3);
            int mo = mbase + ni * 8 + t4 * 2;
            if (own0) {
                float2 v; v.x = d0; v.y = d1;
                *(float2*)&g_owncos[(size_t)(n0 + p0) * TWOS + mo] = v;
            }
            if (own1) {
                float2 v; v.x = d2; v.y = d3;
                *(float2*)&g_owncos[(size_t)(n0 + p1) * TWOS + mo] = v;
            }
        }
        s0 += __shfl_xor_sync(0xffffffffu, s0, 1);
        s0 += __shfl_xor_sync(0xffffffffu, s0, 2);
        s1 += __shfl_xor_sync(0xffffffffu, s1, 1);
        s1 += __shfl_xor_sync(0xffffffffu, s1, 2);
        if (t4 == 0) {
            atomicAdd(&s_rowsum[p0], s0);
            atomicAdd(&s_rowsum[p1], s1);
            if (own0) atomicAdd(&s_blksum[p0], s0);
            if (own1) atomicAdd(&s_blksum[p1], s1);
        }
    }
    __syncthreads();
    if (tid < 128) {
        atomicAdd(&g_total[n0 + tid], s_rowsum[tid]);
        float bsv = s_blksum[tid];
        if (bsv != 0.0f) atomicAdd(&g_blocksum[n0 + tid], bsv);
    }
}

// ---------------------------------------------------------------------------
// K3: one warp per pixel. down = total - blocksum; only the wm-selected
// half (256 values): sum -log(pos/(pos+down+eps)+eps).
// ---------------------------------------------------------------------------
__global__ void k_terms(const unsigned char* __restrict__ mask,
                        const int* __restrict__ wm) {
    int gw   = (blockIdx.x * blockDim.x + threadIdx.x) >> 5;
    int lane = threadIdx.x & 31;
    if (gw >= NN) return;
    int n = gw;

    int wv = wm[n];
    int hb = (wv == 1) ? 0 : SS;   // wm==1 -> net0 -> first half
    float down = g_total[n] - g_blocksum[n];

    float ts = 0.0f;
    #pragma unroll
    for (int k = 0; k < 8; k++) {
        float c = g_owncos[(size_t)n * TWOS + hb + lane + 32 * k];
        float pos = fexp2c(c);
        float r = pos / (pos + down + 1e-12f);
        ts += -logf(r + 1e-12f);
    }
    #pragma unroll
    for (int o = 16; o > 0; o >>= 1) ts += __shfl_xor_sync(0xffffffffu, ts, o);

    if (lane == 0) g_pixterm[n] = mask[n] ? ts : 0.0f;
}

// ---------------------------------------------------------------------------
// K4: per-class reduction -> final scalar.
// ---------------------------------------------------------------------------
__global__ void k_final(const int* __restrict__ labels,
                        const unsigned char* __restrict__ mask,
                        float* __restrict__ out) {
    __shared__ float contrib[CC];
    __shared__ int   cnt[CC];
    int t = threadIdx.x;
    if (t < CC) { contrib[t] = 0.0f; cnt[t] = 0; }
    __syncthreads();
    for (int n = t; n < NN; n += blockDim.x) {
        if (mask[n]) {
            int c = labels[n];
            atomicAdd(&contrib[c], g_pixterm[n]);
            atomicAdd(&cnt[c], 1);
        }
    }
    __syncthreads();
    if (t == 0) {
        float loss = 0.0f, ccount = 0.0f;
        for (int i = 0; i < CC; i++) {
            if (cnt[i] > 0) {
                loss += contrib[i] / ((float)cnt[i] * (float)SS);
                ccount += 1.0f;
            }
        }
        out[0] = loss / fmaxf(ccount, 1.0f);
    }
}

// ---------------------------------------------------------------------------
extern "C" void kernel_launch(void* const* d_in, const int* in_sizes, int n_in,
                              void* d_out, int out_size) {
    const float*         mem    = (const float*)d_in[0];         // (19,512,256)
    const float*         pred   = (const float*)d_in[1];         // (4,256,64,64)
    const int*           labels = (const int*)d_in[2];           // (4,64,64)
    const unsigned char* mask   = (const unsigned char*)d_in[3]; // bool (1B)
    const int*           wm     = (const int*)d_in[4];           // (4,64,64)
    float*               out    = (float*)d_out;

    (void)in_sizes; (void)n_in; (void)out_size;

    cudaFuncSetAttribute(k_gemm, cudaFuncAttributeMaxDynamicSharedMemorySize, SM_TOTAL);

    k_prep_feats<<<dim3(BB, HH / 4), 256>>>(pred);
    k_prep_mem<<<MM, 128>>>(mem);
    k_gemm<<<dim3(MM / 256, NN / 128), 256, SM_TOTAL>>>(labels);
    k_terms<<<NN / 8, 256>>>(mask, wm);
    k_final<<<1, 256>>>(labels, mask, out);
}

// round 9
// speedup vs baseline: 1.1728x; 1.1728x over previous
#include <cuda_runtime.h>
#include <cuda_bf16.h>
#include <math.h>
#include <stdint.h>

// Problem constants (fixed shapes)
#define BB 4
#define HH 64
#define WW 64
#define FF 256
#define CC 19
#define SS 256
#define TWOS (2*SS)            // 512
#define NN (BB*HH*WW)          // 16384 pixels
#define MM (CC*TWOS)           // 9728 memory vectors

// Scratch (static device globals; no allocation at runtime)
__device__ __nv_bfloat16 g_A[NN * FF];   // normalized feats, [n][f] row-major (8 MB)
__device__ __nv_bfloat16 g_Bm[MM * FF];  // normalized memory, [m][f] row-major (5 MB)
__device__ float g_total[NN];            // per-pixel sum of exp(cos/temp)
__device__ float g_blocksum[NN];         // per-pixel own-block sum of exp
__device__ float g_owncos[NN * TWOS];    // per-pixel own-class-block cos (33.5 MB)
__device__ float g_pixterm[NN];          // per-pixel positive-term sum

// ---------------------------------------------------------------------------
// exp(2*c) via MUFU: exp(2c) = 2^(2c*log2 e). ex2.approx rel err ~1e-6 here.
// ---------------------------------------------------------------------------
__device__ __forceinline__ float fexp2c(float c) {
    float y = c * 2.8853900817779268f;   // 2 * log2(e)
    float r;
    asm("ex2.approx.f32 %0, %1;" : "=f"(r) : "f"(y));
    return r;
}

__device__ __forceinline__ void cp16(uint32_t smem_dst, const void* gsrc) {
    asm volatile("cp.async.cg.shared.global [%0], [%1], 16;\n" :: "r"(smem_dst), "l"(gsrc));
}

__device__ __forceinline__ uint32_t smem_u32(const void* p) {
    uint32_t a;
    asm("{ .reg .u64 t; cvta.to.shared.u64 t, %1; cvt.u32.u64 %0, t; }" : "=r"(a) : "l"(p));
    return a;
}

__device__ __forceinline__ void ldm_x4(uint32_t* r, uint32_t addr) {
    asm volatile("ldmatrix.sync.aligned.m8n8.x4.shared.b16 {%0,%1,%2,%3}, [%4];"
        : "=r"(r[0]), "=r"(r[1]), "=r"(r[2]), "=r"(r[3]) : "r"(addr));
}

__device__ __forceinline__ void mma16816(float* d, const uint32_t* a, const uint32_t* b) {
    asm volatile(
        "mma.sync.aligned.m16n8k16.row.col.f32.bf16.bf16.f32 "
        "{%0,%1,%2,%3}, {%4,%5,%6,%7}, {%8,%9}, {%0,%1,%2,%3};\n"
        : "+f"(d[0]), "+f"(d[1]), "+f"(d[2]), "+f"(d[3])
        : "r"(a[0]), "r"(a[1]), "r"(a[2]), "r"(a[3]), "r"(b[0]), "r"(b[1]));
}

// ---------------------------------------------------------------------------
// K1a: normalize feats. pred_rep is (B,F,H,W). Write bf16 [n][f] row-major.
// Also zero g_total/g_blocksum (rewritten each launch -> graph-deterministic).
// ---------------------------------------------------------------------------
__global__ void k_prep_feats(const float* __restrict__ pred) {
    int t = threadIdx.x;
    int w = t & 63;
    int h = blockIdx.y * 4 + (t >> 6);
    int b = blockIdx.x;
    int n = (b * HH + h) * WW + w;
    const float* base = pred + (size_t)b * FF * HH * WW + h * WW + w;

    float sumsq = 0.0f;
    #pragma unroll 8
    for (int f = 0; f < FF; f++) {
        float v = base[f * (HH * WW)];
        sumsq += v * v;
    }
    float inv = rsqrtf(sumsq);

    for (int f0 = 0; f0 < FF; f0 += 8) {
        __nv_bfloat16 h8[8];
        #pragma unroll
        for (int j = 0; j < 8; j++)
            h8[j] = __float2bfloat16(base[(f0 + j) * (HH * WW)] * inv);
        *(uint4*)&g_A[n * FF + f0] = *(const uint4*)h8;
    }
    g_total[n] = 0.0f;
    g_blocksum[n] = 0.0f;
}

// ---------------------------------------------------------------------------
// K1b: normalize memory rows -> bf16 [m][f]. One block (128 thr) per row.
// ---------------------------------------------------------------------------
__global__ void k_prep_mem(const float* __restrict__ mem) {
    __shared__ float red[4];
    int m = blockIdx.x;
    int t = threadIdx.x;
    float2 v = *(const float2*)&mem[m * FF + 2 * t];
    float p = v.x * v.x + v.y * v.y;
    #pragma unroll
    for (int o = 16; o > 0; o >>= 1) p += __shfl_down_sync(0xffffffffu, p, o);
    if ((t & 31) == 0) red[t >> 5] = p;
    __syncthreads();
    float inv = rsqrtf(red[0] + red[1] + red[2] + red[3]);
    __nv_bfloat162 o2;
    o2.x = __float2bfloat16(v.x * inv);
    o2.y = __float2bfloat16(v.y * inv);
    *(__nv_bfloat162*)&g_Bm[m * FF + 2 * t] = o2;
}

// ---------------------------------------------------------------------------
// K2: bf16 HMMA GEMM. CTA tile 128 pix x 128 mem, 128 threads (4 warps,
// 2x2 grid), warp tile 64x64. BK=64, 3-stage cp.async pipeline (one
// __syncthreads per stage), ldmatrix + XOR swizzle. 2 CTAs/SM.
// Epilogue: MUFU exp row sums + own-block sum + own-class cos scatter.
// ---------------------------------------------------------------------------
// Dynamic smem (bytes): labels[128]@0, rowsum@512, blksum@1024,
// A stages @2048 (3 x 16KB), B stages @51200 (3 x 16KB). Total 100352.
#define SM_LAB   0
#define SM_PART  512
#define SM_BPART 1024
#define SM_A     2048
#define SM_B     (2048 + 3*16384)
#define SM_TOTAL (2048 + 6*16384)

__global__ __launch_bounds__(128, 2) void k_gemm(const int* __restrict__ labels) {
    extern __shared__ __align__(1024) char dsm[];
    uint32_t sb = smem_u32(dsm);

    int tid = threadIdx.x;
    int m0 = blockIdx.x * 128;
    int n0 = blockIdx.y * 128;
    int wid = tid >> 5, lane = tid & 31;
    int wmw = wid & 1;          // pixel-dir warp (2): rows [wmw*64, +64)
    int wnw = wid >> 1;         // mem-dir warp (2): cols [wnw*64, +64)
    int g = lane >> 2, t4 = lane & 3;
    int l15 = lane & 15, l16 = lane >> 4;

    float* s_rowsum = (float*)(dsm + SM_PART);
    float* s_blksum = (float*)(dsm + SM_BPART);
    int*   s_lab    = (int*)(dsm + SM_LAB);

    s_rowsum[tid] = 0.0f;
    s_blksum[tid] = 0.0f;
    s_lab[tid] = labels[n0 + tid];

    float acc[4][8][4];
    #pragma unroll
    for (int mi = 0; mi < 4; mi++)
        #pragma unroll
        for (int ni = 0; ni < 8; ni++)
            #pragma unroll
            for (int q = 0; q < 4; q++) acc[mi][ni][q] = 0.0f;

    // Fill one BK=64 stage: A 1024 + B 1024 16B-chunks over 128 threads.
#define ISSUE(IT, BUF) do {                                                     \
        int k0_ = (IT) * 64;                                                    \
        _Pragma("unroll")                                                       \
        for (int r_ = 0; r_ < 8; r_++) {                                        \
            int id = tid + r_ * 128;          /* 0..1023 */                     \
            int row = id >> 3, c = id & 7;                                      \
            int sw = (c ^ (row & 7)) << 4;                                      \
            cp16(sb + SM_A + (BUF) * 16384 + row * 128 + sw,                    \
                 &g_A[(size_t)(n0 + row) * FF + k0_ + c * 8]);                  \
            cp16(sb + SM_B + (BUF) * 16384 + row * 128 + sw,                    \
                 &g_Bm[(size_t)(m0 + row) * FF + k0_ + c * 8]);                 \
        } } while (0)

    ISSUE(0, 0);
    asm volatile("cp.async.commit_group;\n");
    ISSUE(1, 1);
    asm volatile("cp.async.commit_group;\n");

    #pragma unroll
    for (int it = 0; it < 4; it++) {
        if (it < 3) asm volatile("cp.async.wait_group 1;\n" ::: "memory");
        else        asm volatile("cp.async.wait_group 0;\n" ::: "memory");
        __syncthreads();
        if (it < 2) {
            ISSUE(it + 2, (it + 2) % 3);
            asm volatile("cp.async.commit_group;\n");
        }

        int buf = it % 3;
        uint32_t Ab = sb + SM_A + buf * 16384;
        uint32_t Bb = sb + SM_B + buf * 16384;
        #pragma unroll
        for (int ks = 0; ks < 4; ks++) {
            int kc = ks * 2 + l16;
            uint32_t a[4][4], b[4][4];
            #pragma unroll
            for (int mi = 0; mi < 4; mi++) {
                int row = wmw * 64 + mi * 16 + l15;
                ldm_x4(a[mi], Ab + row * 128 + ((kc ^ (row & 7)) << 4));
            }
            #pragma unroll
            for (int nj = 0; nj < 4; nj++) {
                int row = wnw * 64 + nj * 16 + l15;
                ldm_x4(b[nj], Bb + row * 128 + ((kc ^ (row & 7)) << 4));
            }
            #pragma unroll
            for (int mi = 0; mi < 4; mi++)
                #pragma unroll
                for (int nj = 0; nj < 4; nj++) {
                    uint32_t b0[2] = { b[nj][0], b[nj][2] };
                    uint32_t b1[2] = { b[nj][1], b[nj][3] };
                    mma16816(acc[mi][2 * nj],     a[mi], b0);
                    mma16816(acc[mi][2 * nj + 1], a[mi], b1);
                }
        }
    }
#undef ISSUE
    __syncthreads();

    // Epilogue: MUFU exp + row sums + own-block sums + own-class cos scatter.
    // 128-aligned m-window always lies inside one 512-wide class block.
    int cls = m0 >> 9;
    int mbase = (m0 & 511) + wnw * 64;

    #pragma unroll
    for (int mi = 0; mi < 4; mi++) {
        int p0 = wmw * 64 + mi * 16 + g;
        int p1 = p0 + 8;
        bool own0 = (s_lab[p0] == cls);
        bool own1 = (s_lab[p1] == cls);
        float s0 = 0.0f, s1 = 0.0f;
        #pragma unroll
        for (int ni = 0; ni < 8; ni++) {
            float d0 = acc[mi][ni][0], d1 = acc[mi][ni][1];
            float d2 = acc[mi][ni][2], d3 = acc[mi][ni][3];
            s0 += fexp2c(d0) + fexp2c(d1);
            s1 += fexp2c(d2) + fexp2c(d3);
            int mo = mbase + ni * 8 + t4 * 2;
            if (own0) {
                float2 v; v.x = d0; v.y = d1;
                *(float2*)&g_owncos[(size_t)(n0 + p0) * TWOS + mo] = v;
            }
            if (own1) {
                float2 v; v.x = d2; v.y = d3;
                *(float2*)&g_owncos[(size_t)(n0 + p1) * TWOS + mo] = v;
            }
        }
        s0 += __shfl_xor_sync(0xffffffffu, s0, 1);
        s0 += __shfl_xor_sync(0xffffffffu, s0, 2);
        s1 += __shfl_xor_sync(0xffffffffu, s1, 1);
        s1 += __shfl_xor_sync(0xffffffffu, s1, 2);
        if (t4 == 0) {
            atomicAdd(&s_rowsum[p0], s0);
            atomicAdd(&s_rowsum[p1], s1);
            if (own0) atomicAdd(&s_blksum[p0], s0);
            if (own1) atomicAdd(&s_blksum[p1], s1);
        }
    }
    __syncthreads();
    atomicAdd(&g_total[n0 + tid], s_rowsum[tid]);
    {
        float bsv = s_blksum[tid];
        if (bsv != 0.0f) atomicAdd(&g_blocksum[n0 + tid], bsv);
    }
}

// ---------------------------------------------------------------------------
// K3: one warp per pixel. down = total - blocksum; only the wm-selected
// half (256 values): sum -log(pos/(pos+down+eps)+eps).
// ---------------------------------------------------------------------------
__global__ void k_terms(const unsigned char* __restrict__ mask,
                        const int* __restrict__ wm) {
    int gw   = (blockIdx.x * blockDim.x + threadIdx.x) >> 5;
    int lane = threadIdx.x & 31;
    if (gw >= NN) return;
    int n = gw;

    int wv = wm[n];
    int hb = (wv == 1) ? 0 : SS;   // wm==1 -> net0 -> first half
    float down = g_total[n] - g_blocksum[n];

    float ts = 0.0f;
    #pragma unroll
    for (int k = 0; k < 8; k++) {
        float c = g_owncos[(size_t)n * TWOS + hb + lane + 32 * k];
        float pos = fexp2c(c);
        float r = pos / (pos + down + 1e-12f);
        ts += -logf(r + 1e-12f);
    }
    #pragma unroll
    for (int o = 16; o > 0; o >>= 1) ts += __shfl_xor_sync(0xffffffffu, ts, o);

    if (lane == 0) g_pixterm[n] = mask[n] ? ts : 0.0f;
}

// ---------------------------------------------------------------------------
// K4: per-class reduction -> final scalar.
// ---------------------------------------------------------------------------
__global__ void k_final(const int* __restrict__ labels,
                        const unsigned char* __restrict__ mask,
                        float* __restrict__ out) {
    __shared__ float contrib[CC];
    __shared__ int   cnt[CC];
    int t = threadIdx.x;
    if (t < CC) { contrib[t] = 0.0f; cnt[t] = 0; }
    __syncthreads();
    for (int n = t; n < NN; n += blockDim.x) {
        if (mask[n]) {
            int c = labels[n];
            atomicAdd(&contrib[c], g_pixterm[n]);
            atomicAdd(&cnt[c], 1);
        }
    }
    __syncthreads();
    if (t == 0) {
        float loss = 0.0f, ccount = 0.0f;
        for (int i = 0; i < CC; i++) {
            if (cnt[i] > 0) {
                loss += contrib[i] / ((float)cnt[i] * (float)SS);
                ccount += 1.0f;
            }
        }
        out[0] = loss / fmaxf(ccount, 1.0f);
    }
}

// ---------------------------------------------------------------------------
extern "C" void kernel_launch(void* const* d_in, const int* in_sizes, int n_in,
                              void* d_out, int out_size) {
    const float*         mem    = (const float*)d_in[0];         // (19,512,256)
    const float*         pred   = (const float*)d_in[1];         // (4,256,64,64)
    const int*           labels = (const int*)d_in[2];           // (4,64,64)
    const unsigned char* mask   = (const unsigned char*)d_in[3]; // bool (1B)
    const int*           wm     = (const int*)d_in[4];           // (4,64,64)
    float*               out    = (float*)d_out;

    (void)in_sizes; (void)n_in; (void)out_size;

    cudaFuncSetAttribute(k_gemm, cudaFuncAttributeMaxDynamicSharedMemorySize, SM_TOTAL);

    k_prep_feats<<<dim3(BB, HH / 4), 256>>>(pred);
    k_prep_mem<<<MM, 128>>>(mem);
    k_gemm<<<dim3(MM / 128, NN / 128), 128, SM_TOTAL>>>(labels);
    k_terms<<<NN / 8, 256>>>(mask, wm);
    k_final<<<1, 256>>>(labels, mask, out);
}